// round 1
// baseline (speedup 1.0000x reference)
#include <cuda_runtime.h>
#include <cuda_bf16.h>
#include <cstdint>

// ---------------------------------------------------------------------------
// RingNet = [x, ring3..ring25] -> BN -> 1x1(1248->512) -> ReLU -> BN -> 1x1(512->96)
// Restructured:  SAT box features -> folded GEMM1 -> ReLU -> folded GEMM2
// GEMMs in bf16 hi/lo split (3 products) via mma.sync.m16n8k16 for fp32-class accuracy.
// ---------------------------------------------------------------------------

namespace {
constexpr int Bn = 4, Cn = 96, Hn = 128, Wn = 128;
constexpr int HWn = Hn * Wn;           // 16384
constexpr int Mtot = Bn * HWn;         // 65536
constexpr int K1 = 1248, N1 = 512, N2 = 96;
constexpr int SATR = 129, SATC = 132;  // padded row stride
constexpr float BN_EPS = 1e-5f;
}

// -------------------- device scratch (static, allocation-free) --------------
__device__ float         g_sat[(size_t)Bn * Cn * SATR * SATC];           // ~26 MB
__device__ __nv_bfloat16 g_phi_hi[(size_t)K1 * Mtot];                    // ~164 MB
__device__ __nv_bfloat16 g_phi_lo[(size_t)K1 * Mtot];                    // ~164 MB
__device__ __nv_bfloat16 g_h1_hi[(size_t)N1 * Mtot];                     // ~64 MB
__device__ __nv_bfloat16 g_h1_lo[(size_t)N1 * Mtot];                     // ~64 MB
__device__ __nv_bfloat16 g_W1h[N1 * K1], g_W1l[N1 * K1];
__device__ __nv_bfloat16 g_W2h[N2 * N1], g_W2l[N2 * N1];
__device__ float         g_b1f[N1], g_b2f[N2];

// -------------------- weight folding ----------------------------------------
// Wb[o, j*96+c] = W1[o,j*96+c]*s1[j*96+c] - (j<12 ? W1[o,(j+1)*96+c]*s1[(j+1)*96+c] : 0)
// b1f[o] = b1[o] + sum_c' W1[o,c'] * (beta - mean*s)[c']
__global__ void k_fold1(const float* __restrict__ W1, const float* __restrict__ b1,
                        const float* __restrict__ ga, const float* __restrict__ be,
                        const float* __restrict__ mu, const float* __restrict__ va) {
    int o = blockIdx.x;
    int tid = threadIdx.x;
    float part = 0.f;
    for (int c = tid; c < K1; c += 256) {
        float s  = ga[c] * rsqrtf(va[c] + BN_EPS);
        float sh = be[c] - mu[c] * s;
        float w  = W1[(size_t)o * K1 + c];
        part += w * sh;
        float wb = w * s;
        if (c < K1 - 96) {
            float s2 = ga[c + 96] * rsqrtf(va[c + 96] + BN_EPS);
            wb -= W1[(size_t)o * K1 + c + 96] * s2;
        }
        __nv_bfloat16 hi = __float2bfloat16(wb);
        g_W1h[(size_t)o * K1 + c] = hi;
        g_W1l[(size_t)o * K1 + c] = __float2bfloat16(wb - __bfloat162float(hi));
    }
    __shared__ float red[256];
    red[tid] = part; __syncthreads();
    for (int s = 128; s > 0; s >>= 1) { if (tid < s) red[tid] += red[tid + s]; __syncthreads(); }
    if (tid == 0) g_b1f[o] = b1[o] + red[0];
}

__global__ void k_fold2(const float* __restrict__ W2, const float* __restrict__ b2,
                        const float* __restrict__ ga, const float* __restrict__ be,
                        const float* __restrict__ mu, const float* __restrict__ va) {
    int o = blockIdx.x;
    int tid = threadIdx.x;
    float part = 0.f;
    for (int c = tid; c < N1; c += 256) {
        float s  = ga[c] * rsqrtf(va[c] + BN_EPS);
        float sh = be[c] - mu[c] * s;
        float w  = W2[(size_t)o * N1 + c];
        part += w * sh;
        float wf = w * s;
        __nv_bfloat16 hi = __float2bfloat16(wf);
        g_W2h[(size_t)o * N1 + c] = hi;
        g_W2l[(size_t)o * N1 + c] = __float2bfloat16(wf - __bfloat162float(hi));
    }
    __shared__ float red[256];
    red[tid] = part; __syncthreads();
    for (int s = 128; s > 0; s >>= 1) { if (tid < s) red[tid] += red[tid + s]; __syncthreads(); }
    if (tid == 0) g_b2f[o] = b2[o] + red[0];
}

// -------------------- summed-area tables -------------------------------------
// S[img][r][cx] = sum over input rows < r, cols < cx   (exclusive 2D prefix)
__global__ void k_sat_rows(const float* __restrict__ x) {
    int idx = blockIdx.x * blockDim.x + threadIdx.x;
    if (idx >= Bn * Cn * SATR) return;
    int img = idx / SATR;
    int r   = idx % SATR;
    float* S = g_sat + (size_t)img * SATR * SATC;
    if (r == 0) {
        for (int cx = 0; cx <= 128; cx++) S[cx] = 0.f;
    } else {
        const float* row = x + (size_t)img * HWn + (size_t)(r - 1) * Wn;
        float* Sr = S + (size_t)r * SATC;
        Sr[0] = 0.f;
        float acc = 0.f;
        for (int xx = 0; xx < Wn; xx++) { acc += row[xx]; Sr[xx + 1] = acc; }
    }
}

__global__ void k_sat_cols() {
    int idx = blockIdx.x * blockDim.x + threadIdx.x;
    if (idx >= Bn * Cn * SATR) return;
    int img = idx / SATR;
    int cc  = idx % SATR;
    float* S = g_sat + (size_t)img * SATR * SATC;
    float acc = 0.f;
    for (int r = 1; r <= 128; r++) {
        acc += S[(size_t)r * SATC + cc];
        S[(size_t)r * SATC + cc] = acc;
    }
}

// -------------------- box features phi[k][m] (hi/lo bf16) --------------------
__global__ void k_features(const float* __restrict__ x) {
    int k = blockIdx.y;                       // 0..1247
    int m = blockIdx.x * blockDim.x + threadIdx.x;  // 0..65535
    int j = k / 96, c = k - j * 96;
    int b = m >> 14, pix = m & (HWn - 1);
    int y = pix >> 7, xx = pix & 127;
    float v;
    if (j == 0) {
        v = x[(size_t)(b * Cn + c) * HWn + pix];
    } else {
        const float* S = g_sat + (size_t)(b * Cn + c) * SATR * SATC;
        int rlo = max(y - j, 0), rhi = min(y + j + 1, 128);
        int clo = max(xx - j, 0), chi = min(xx + j + 1, 128);
        v = S[(size_t)rhi * SATC + chi] - S[(size_t)rlo * SATC + chi]
          - S[(size_t)rhi * SATC + clo] + S[(size_t)rlo * SATC + clo];
    }
    __nv_bfloat16 hi = __float2bfloat16(v);
    g_phi_hi[(size_t)k * Mtot + m] = hi;
    g_phi_lo[(size_t)k * Mtot + m] = __float2bfloat16(v - __bfloat162float(hi));
}

// -------------------- GEMM via mma.sync bf16, hi/lo 3-product ----------------
__device__ __forceinline__ void mma16816(float* c, const uint32_t* a, const uint32_t* b) {
    asm volatile(
        "mma.sync.aligned.m16n8k16.row.col.f32.bf16.bf16.f32 "
        "{%0,%1,%2,%3},{%4,%5,%6,%7},{%8,%9},{%0,%1,%2,%3};\n"
        : "+f"(c[0]), "+f"(c[1]), "+f"(c[2]), "+f"(c[3])
        : "r"(a[0]), "r"(a[1]), "r"(a[2]), "r"(a[3]), "r"(b[0]), "r"(b[1]));
}

// MODE 1: C[n,m] = relu(sum_k W1[n,k]*phi[k,m] + b1f[n]) -> split to g_h1 hi/lo
// MODE 2: out    =       sum_k W2[n,k]*h1[k,m]  + b2f[n] -> fp32 d_out (B,96,HW)
template <int MODE>
__global__ void __launch_bounds__(256) k_gemm(float* __restrict__ d_out) {
    constexpr int KK = (MODE == 1) ? K1 : N1;
    constexpr int BN = (MODE == 1) ? 128 : 96;
    constexpr int NT = BN / 32;        // n-tiles per warp (4 or 3)
    constexpr int PAD = 18;

    const __nv_bfloat16* __restrict__ Ahi = (MODE == 1) ? g_phi_hi : g_h1_hi;
    const __nv_bfloat16* __restrict__ Alo = (MODE == 1) ? g_phi_lo : g_h1_lo;
    const __nv_bfloat16* __restrict__ Bhi = (MODE == 1) ? g_W1h : g_W2h;
    const __nv_bfloat16* __restrict__ Blo = (MODE == 1) ? g_W1l : g_W2l;
    const float* __restrict__ bias = (MODE == 1) ? g_b1f : g_b2f;

    __shared__ __nv_bfloat16 sAhi[128][PAD], sAlo[128][PAD];
    __shared__ __nv_bfloat16 sBhi[BN][PAD],  sBlo[BN][PAD];

    int tid = threadIdx.x, lane = tid & 31, wid = tid >> 5;
    int wm = (wid & 1) * 64;             // warp m offset (2 warps in m)
    int wn = (wid >> 1) * (BN / 4);      // warp n offset (4 warps in n)
    int g = lane >> 2, t = lane & 3;
    int m0 = blockIdx.x * 128;
    int n0 = blockIdx.y * BN;

    float acc[4][NT][4];
    #pragma unroll
    for (int mt = 0; mt < 4; mt++)
        #pragma unroll
        for (int nt = 0; nt < NT; nt++)
            #pragma unroll
            for (int r = 0; r < 4; r++) acc[mt][nt][r] = 0.f;

    for (int kb = 0; kb < KK; kb += 16) {
        // stage A tile [16k x 128m] -> smem transposed [m][k]
        #pragma unroll 4
        for (int i = tid; i < 16 * 64; i += 256) {
            int kk = i >> 6;
            int wo = (i & 63) << 1;
            __nv_bfloat162 vh = *(const __nv_bfloat162*)(Ahi + (size_t)(kb + kk) * Mtot + m0 + wo);
            __nv_bfloat162 vl = *(const __nv_bfloat162*)(Alo + (size_t)(kb + kk) * Mtot + m0 + wo);
            sAhi[wo][kk] = vh.x; sAhi[wo + 1][kk] = vh.y;
            sAlo[wo][kk] = vl.x; sAlo[wo + 1][kk] = vl.y;
        }
        // stage B tile [BN n x 16 k]
        #pragma unroll 4
        for (int i = tid; i < BN * 8; i += 256) {
            int n = i >> 3;
            int w = (i & 7) << 1;
            *(__nv_bfloat162*)&sBhi[n][w] = *(const __nv_bfloat162*)(Bhi + (size_t)(n0 + n) * KK + kb + w);
            *(__nv_bfloat162*)&sBlo[n][w] = *(const __nv_bfloat162*)(Blo + (size_t)(n0 + n) * KK + kb + w);
        }
        __syncthreads();

        uint32_t ah[4][4], al[4][4], bh[NT][2], bl[NT][2];
        #pragma unroll
        for (int mt = 0; mt < 4; mt++) {
            int r = wm + mt * 16 + g;
            ah[mt][0] = *(const uint32_t*)&sAhi[r][2 * t];
            ah[mt][1] = *(const uint32_t*)&sAhi[r + 8][2 * t];
            ah[mt][2] = *(const uint32_t*)&sAhi[r][2 * t + 8];
            ah[mt][3] = *(const uint32_t*)&sAhi[r + 8][2 * t + 8];
            al[mt][0] = *(const uint32_t*)&sAlo[r][2 * t];
            al[mt][1] = *(const uint32_t*)&sAlo[r + 8][2 * t];
            al[mt][2] = *(const uint32_t*)&sAlo[r][2 * t + 8];
            al[mt][3] = *(const uint32_t*)&sAlo[r + 8][2 * t + 8];
        }
        #pragma unroll
        for (int nt = 0; nt < NT; nt++) {
            int r = wn + nt * 8 + g;
            bh[nt][0] = *(const uint32_t*)&sBhi[r][2 * t];
            bh[nt][1] = *(const uint32_t*)&sBhi[r][2 * t + 8];
            bl[nt][0] = *(const uint32_t*)&sBlo[r][2 * t];
            bl[nt][1] = *(const uint32_t*)&sBlo[r][2 * t + 8];
        }
        #pragma unroll
        for (int mt = 0; mt < 4; mt++)
            #pragma unroll
            for (int nt = 0; nt < NT; nt++) {
                mma16816(acc[mt][nt], ah[mt], bh[nt]);   // hi*hi
                mma16816(acc[mt][nt], ah[mt], bl[nt]);   // hi*lo
                mma16816(acc[mt][nt], al[mt], bh[nt]);   // lo*hi
            }
        __syncthreads();
    }

    // epilogue
    #pragma unroll
    for (int mt = 0; mt < 4; mt++) {
        int mr0 = m0 + wm + mt * 16 + g;
        #pragma unroll
        for (int nt = 0; nt < NT; nt++) {
            int nc0 = n0 + wn + nt * 8 + 2 * t;
            #pragma unroll
            for (int r = 0; r < 4; r++) {
                int mrow = mr0 + ((r >= 2) ? 8 : 0);
                int ncol = nc0 + (r & 1);
                float v = acc[mt][nt][r] + bias[ncol];
                if (MODE == 1) {
                    v = fmaxf(v, 0.f);
                    __nv_bfloat16 hi = __float2bfloat16(v);
                    g_h1_hi[(size_t)ncol * Mtot + mrow] = hi;
                    g_h1_lo[(size_t)ncol * Mtot + mrow] =
                        __float2bfloat16(v - __bfloat162float(hi));
                } else {
                    int b = mrow >> 14, pix = mrow & (HWn - 1);
                    d_out[((size_t)b * N2 + ncol) * HWn + pix] = v;
                }
            }
        }
    }
}

// -------------------- launch ------------------------------------------------
extern "C" void kernel_launch(void* const* d_in, const int* in_sizes, int n_in,
                              void* d_out, int out_size) {
    (void)in_sizes; (void)n_in; (void)out_size;
    const float* x   = (const float*)d_in[0];
    const float* g1  = (const float*)d_in[1];
    const float* be1 = (const float*)d_in[2];
    const float* mu1 = (const float*)d_in[3];
    const float* va1 = (const float*)d_in[4];
    const float* W1  = (const float*)d_in[5];
    const float* b1  = (const float*)d_in[6];
    const float* g2  = (const float*)d_in[7];
    const float* be2 = (const float*)d_in[8];
    const float* mu2 = (const float*)d_in[9];
    const float* va2 = (const float*)d_in[10];
    const float* W2  = (const float*)d_in[11];
    const float* b2  = (const float*)d_in[12];

    k_fold1<<<N1, 256>>>(W1, b1, g1, be1, mu1, va1);
    k_fold2<<<N2, 256>>>(W2, b2, g2, be2, mu2, va2);

    int nsat = Bn * Cn * SATR;
    k_sat_rows<<<(nsat + 127) / 128, 128>>>(x);
    k_sat_cols<<<(nsat + 127) / 128, 128>>>();

    k_features<<<dim3(Mtot / 256, K1), 256>>>(x);

    k_gemm<1><<<dim3(Mtot / 128, N1 / 128), 256>>>(nullptr);
    k_gemm<2><<<dim3(Mtot / 128, 1), 256>>>((float*)d_out);
}

// round 3
// speedup vs baseline: 1.3443x; 1.3443x over previous
#include <cuda_runtime.h>
#include <cuda_bf16.h>
#include <cstdint>

// ---------------------------------------------------------------------------
// RingNet restructured: SAT box features -> folded GEMM1 -> ReLU -> folded
// GEMM2, bf16 hi/lo 3-product via mma.sync (HMMA), cp.async double-buffered.
// (tcgen05 unavailable: harness emits compute_103 PTX, 'a'-features rejected.)
// ---------------------------------------------------------------------------

namespace {
constexpr int Bn = 4, Cn = 96, Hn = 128, Wn = 128;
constexpr int HWn = Hn * Wn;           // 16384
constexpr int Mtot = Bn * HWn;         // 65536
constexpr int K1 = 1248, N1 = 512, N2 = 96;
constexpr int KKP = 1280;              // K1 padded to mult of 32
constexpr int SATR = 129, SATC = 132;
constexpr float BN_EPS = 1e-5f;
}

// -------------------- device scratch ----------------------------------------
__device__ float         g_sat[(size_t)Bn * Cn * SATR * SATC];
__device__ __nv_bfloat16 g_phi_hi[(size_t)Mtot * KKP];   // [m][k] k-contiguous
__device__ __nv_bfloat16 g_phi_lo[(size_t)Mtot * KKP];
__device__ __nv_bfloat16 g_h1_hi[(size_t)Mtot * N1];     // [m][n] n-contiguous
__device__ __nv_bfloat16 g_h1_lo[(size_t)Mtot * N1];
__device__ __nv_bfloat16 g_W1h[N1 * KKP], g_W1l[N1 * KKP];
__device__ __nv_bfloat16 g_W2h[N2 * N1],  g_W2l[N2 * N1];
__device__ float         g_b1f[N1], g_b2f[N2];

// -------------------- helpers ------------------------------------------------
__device__ __forceinline__ uint32_t smem_u32(const void* p) {
    uint32_t a;
    asm("{ .reg .u64 t; cvta.to.shared.u64 t, %1; cvt.u32.u64 %0, t; }" : "=r"(a) : "l"(p));
    return a;
}
__device__ __forceinline__ void cpa16(uint32_t dst, const void* src) {
    asm volatile("cp.async.cg.shared.global [%0], [%1], 16;" :: "r"(dst), "l"(src));
}
__device__ __forceinline__ void mma16816(float* c, const uint32_t* a, const uint32_t* b) {
    asm volatile(
        "mma.sync.aligned.m16n8k16.row.col.f32.bf16.bf16.f32 "
        "{%0,%1,%2,%3},{%4,%5,%6,%7},{%8,%9},{%0,%1,%2,%3};\n"
        : "+f"(c[0]), "+f"(c[1]), "+f"(c[2]), "+f"(c[3])
        : "r"(a[0]), "r"(a[1]), "r"(a[2]), "r"(a[3]), "r"(b[0]), "r"(b[1]));
}

// -------------------- weight folding ----------------------------------------
__global__ void k_fold1(const float* __restrict__ W1, const float* __restrict__ b1,
                        const float* __restrict__ ga, const float* __restrict__ be,
                        const float* __restrict__ mu, const float* __restrict__ va) {
    int o = blockIdx.x, tid = threadIdx.x;
    float part = 0.f;
    for (int c = tid; c < KKP; c += 256) {
        float wb = 0.f;
        if (c < K1) {
            float s  = ga[c] * rsqrtf(va[c] + BN_EPS);
            float w  = W1[(size_t)o * K1 + c];
            part += w * (be[c] - mu[c] * s);
            wb = w * s;
            if (c < K1 - 96) {
                float s2 = ga[c + 96] * rsqrtf(va[c + 96] + BN_EPS);
                wb -= W1[(size_t)o * K1 + c + 96] * s2;
            }
        }
        __nv_bfloat16 hi = __float2bfloat16(wb);
        g_W1h[(size_t)o * KKP + c] = hi;
        g_W1l[(size_t)o * KKP + c] = __float2bfloat16(wb - __bfloat162float(hi));
    }
    __shared__ float red[256];
    red[tid] = part; __syncthreads();
    for (int s = 128; s > 0; s >>= 1) { if (tid < s) red[tid] += red[tid + s]; __syncthreads(); }
    if (tid == 0) g_b1f[o] = b1[o] + red[0];
}

__global__ void k_fold2(const float* __restrict__ W2, const float* __restrict__ b2,
                        const float* __restrict__ ga, const float* __restrict__ be,
                        const float* __restrict__ mu, const float* __restrict__ va) {
    int o = blockIdx.x, tid = threadIdx.x;
    float part = 0.f;
    for (int c = tid; c < N1; c += 256) {
        float s  = ga[c] * rsqrtf(va[c] + BN_EPS);
        float w  = W2[(size_t)o * N1 + c];
        part += w * (be[c] - mu[c] * s);
        float wf = w * s;
        __nv_bfloat16 hi = __float2bfloat16(wf);
        g_W2h[(size_t)o * N1 + c] = hi;
        g_W2l[(size_t)o * N1 + c] = __float2bfloat16(wf - __bfloat162float(hi));
    }
    __shared__ float red[256];
    red[tid] = part; __syncthreads();
    for (int s = 128; s > 0; s >>= 1) { if (tid < s) red[tid] += red[tid + s]; __syncthreads(); }
    if (tid == 0) g_b2f[o] = b2[o] + red[0];
}

// -------------------- summed-area tables -------------------------------------
__global__ void k_sat_rows(const float* __restrict__ x) {
    int idx = blockIdx.x * blockDim.x + threadIdx.x;
    if (idx >= Bn * Cn * SATR) return;
    int img = idx / SATR, r = idx % SATR;
    float* S = g_sat + (size_t)img * SATR * SATC;
    if (r == 0) { for (int cx = 0; cx <= 128; cx++) S[cx] = 0.f; }
    else {
        const float* row = x + (size_t)img * HWn + (size_t)(r - 1) * Wn;
        float* Sr = S + (size_t)r * SATC;
        Sr[0] = 0.f;
        float acc = 0.f;
        for (int xx = 0; xx < Wn; xx++) { acc += row[xx]; Sr[xx + 1] = acc; }
    }
}
__global__ void k_sat_cols() {
    int idx = blockIdx.x * blockDim.x + threadIdx.x;
    if (idx >= Bn * Cn * SATR) return;
    int img = idx / SATR, cc = idx % SATR;
    float* S = g_sat + (size_t)img * SATR * SATC;
    float acc = 0.f;
    for (int r = 1; r <= 128; r++) {
        acc += S[(size_t)r * SATC + cc];
        S[(size_t)r * SATC + cc] = acc;
    }
}

// -------------------- features: phi[m][k] hi/lo, k contiguous ----------------
__global__ void k_features(const float* __restrict__ x) {
    __shared__ float sv[32][65];
    int mt = blockIdx.x;                 // 64 m each
    int kt = blockIdx.y;                 // 32 k each
    int tid = threadIdx.x;
    {
        int m_in = tid & 63;
        int kq4  = tid >> 6;             // 0..3
        int m = mt * 64 + m_in;
        int b = m >> 14, pix = m & (HWn - 1), y = pix >> 7, xx = pix & 127;
        #pragma unroll
        for (int it = 0; it < 8; it++) {
            int k_in = it * 4 + kq4;
            int k = kt * 32 + k_in;
            float v = 0.f;
            if (k < K1) {
                int j = k / 96, c = k - j * 96;
                if (j == 0) v = x[(size_t)(b * Cn + c) * HWn + pix];
                else {
                    const float* S = g_sat + (size_t)(b * Cn + c) * SATR * SATC;
                    int rlo = max(y - j, 0),  rhi = min(y + j + 1, 128);
                    int clo = max(xx - j, 0), chi = min(xx + j + 1, 128);
                    v = S[(size_t)rhi * SATC + chi] - S[(size_t)rlo * SATC + chi]
                      - S[(size_t)rhi * SATC + clo] + S[(size_t)rlo * SATC + clo];
                }
            }
            sv[k_in][m_in] = v;
        }
    }
    __syncthreads();
    {
        int m2 = tid >> 2;               // 0..63
        int k0 = (tid & 3) * 8;          // 8 k per thread
        uint32_t ph[4], pl[4];
        #pragma unroll
        for (int i = 0; i < 4; i++) {
            float v0 = sv[k0 + 2 * i][m2], v1 = sv[k0 + 2 * i + 1][m2];
            __nv_bfloat16 h0 = __float2bfloat16(v0), h1 = __float2bfloat16(v1);
            __nv_bfloat162 hh; hh.x = h0; hh.y = h1;
            ph[i] = *(uint32_t*)&hh;
            __nv_bfloat162 ll;
            ll.x = __float2bfloat16(v0 - __bfloat162float(h0));
            ll.y = __float2bfloat16(v1 - __bfloat162float(h1));
            pl[i] = *(uint32_t*)&ll;
        }
        size_t off = (size_t)(mt * 64 + m2) * KKP + kt * 32 + k0;
        *(uint4*)(g_phi_hi + off) = make_uint4(ph[0], ph[1], ph[2], ph[3]);
        *(uint4*)(g_phi_lo + off) = make_uint4(pl[0], pl[1], pl[2], pl[3]);
    }
}

// -------------------- pipelined HMMA GEMM ------------------------------------
// C[128 m, BN n] per CTA. A[m][KK], B[n][KK] (k-contiguous), hi/lo 3-product.
// WM=2 m-warps x WN n-warps; warp tile 64m x (NT*8)n. KC=32 double-buffered.
// MODE 1: relu(v+bias) -> h1 hi/lo [m][N1].  MODE 2: v+bias -> d_out fp32.
template <int KK, int BN, int WN, int MODE>
__global__ void __launch_bounds__(WN * 64, 1) k_gemm(
    const __nv_bfloat16* __restrict__ Ah, const __nv_bfloat16* __restrict__ Al,
    const __nv_bfloat16* __restrict__ Bh, const __nv_bfloat16* __restrict__ Bl,
    const float* __restrict__ bias, float* __restrict__ dout) {
    constexpr int T    = WN * 64;
    constexpr int NT   = BN / (WN * 8);
    constexpr int RS   = 80;                     // 32 elems * 2B + 16B pad
    constexpr int A_TS = 128 * RS;
    constexpr int B_TS = BN * RS;
    constexpr int SS   = 2 * A_TS + 2 * B_TS;
    constexpr int NC   = KK / 32;
    constexpr int AU   = 1024;                   // A 16B-units per stage
    constexpr int BU   = BN * 8;

    extern __shared__ char smem[];
    float* s_bias = (float*)(smem + 2 * SS);
    uint32_t sb = smem_u32(smem);

    int tid = threadIdx.x, wid = tid >> 5, lane = tid & 31;
    int g = lane >> 2, t = lane & 3;
    int wm = (wid & 1) * 64, wn = (wid >> 1) * (NT * 8);
    int m0 = blockIdx.x * 128, n0 = blockIdx.y * BN;

    for (int i = tid; i < BN; i += T) s_bias[i] = bias[n0 + i];

    float acc[4][NT][4];
    #pragma unroll
    for (int mt = 0; mt < 4; mt++)
        #pragma unroll
        for (int nt = 0; nt < NT; nt++)
            #pragma unroll
            for (int r = 0; r < 4; r++) acc[mt][nt][r] = 0.f;

    auto stage = [&](int c, int s) {
        uint32_t base = sb + s * SS;
        int kb = c * 32;
        #pragma unroll
        for (int i = tid; i < AU + BU; i += T) {
            const __nv_bfloat16* src;
            uint32_t doff;
            if (i < AU) {
                int hl = (i >= 512);
                int r = (i & 511) >> 2, u = i & 3;
                src = (hl ? Al : Ah) + (size_t)(m0 + r) * KK + kb + u * 8;
                doff = hl * A_TS + r * RS + u * 16;
            } else {
                int j = i - AU;
                int hl = (j >= BN * 4);
                int q = hl ? j - BN * 4 : j;
                int r = q >> 2, u = q & 3;
                src = (hl ? Bl : Bh) + (size_t)(n0 + r) * KK + kb + u * 8;
                doff = 2 * A_TS + hl * B_TS + r * RS + u * 16;
            }
            cpa16(base + doff, src);
        }
        asm volatile("cp.async.commit_group;" ::: "memory");
    };

    stage(0, 0);
    for (int c = 0; c < NC; c++) {
        int s = c & 1;
        if (c + 1 < NC) {
            stage(c + 1, (c + 1) & 1);
            asm volatile("cp.async.wait_group 1;" ::: "memory");
        } else {
            asm volatile("cp.async.wait_group 0;" ::: "memory");
        }
        __syncthreads();

        const char* base = smem + s * SS;
        #pragma unroll
        for (int ks = 0; ks < 2; ks++) {
            int ck = ks * 32;
            uint32_t ah[4][4], al[4][4], bh[NT][2], bl[NT][2];
            #pragma unroll
            for (int mt = 0; mt < 4; mt++) {
                const char* p = base + (wm + mt * 16 + g) * RS + ck + t * 4;
                ah[mt][0] = *(const uint32_t*)p;
                ah[mt][1] = *(const uint32_t*)(p + 8 * RS);
                ah[mt][2] = *(const uint32_t*)(p + 16);
                ah[mt][3] = *(const uint32_t*)(p + 8 * RS + 16);
                al[mt][0] = *(const uint32_t*)(p + A_TS);
                al[mt][1] = *(const uint32_t*)(p + A_TS + 8 * RS);
                al[mt][2] = *(const uint32_t*)(p + A_TS + 16);
                al[mt][3] = *(const uint32_t*)(p + A_TS + 8 * RS + 16);
            }
            #pragma unroll
            for (int nt = 0; nt < NT; nt++) {
                const char* p = base + 2 * A_TS + (wn + nt * 8 + g) * RS + ck + t * 4;
                bh[nt][0] = *(const uint32_t*)p;
                bh[nt][1] = *(const uint32_t*)(p + 16);
                bl[nt][0] = *(const uint32_t*)(p + B_TS);
                bl[nt][1] = *(const uint32_t*)(p + B_TS + 16);
            }
            #pragma unroll
            for (int mt = 0; mt < 4; mt++)
                #pragma unroll
                for (int nt = 0; nt < NT; nt++) {
                    mma16816(acc[mt][nt], ah[mt], bh[nt]);   // hi*hi
                    mma16816(acc[mt][nt], ah[mt], bl[nt]);   // hi*lo
                    mma16816(acc[mt][nt], al[mt], bh[nt]);   // lo*hi
                }
        }
        __syncthreads();
    }

    // ------- epilogue --------------------------------------------------------
    #pragma unroll
    for (int mt = 0; mt < 4; mt++) {
        int mr = m0 + wm + mt * 16 + g;
        #pragma unroll
        for (int nt = 0; nt < NT; nt++) {
            int ncl = wn + nt * 8 + 2 * t;   // local n (bias idx)
            int nc  = n0 + ncl;              // global n
            #pragma unroll
            for (int h = 0; h < 2; h++) {
                int mrow = mr + h * 8;
                float v0 = acc[mt][nt][2 * h]     + s_bias[ncl];
                float v1 = acc[mt][nt][2 * h + 1] + s_bias[ncl + 1];
                if (MODE == 1) {
                    v0 = fmaxf(v0, 0.f); v1 = fmaxf(v1, 0.f);
                    __nv_bfloat16 h0 = __float2bfloat16(v0), h1 = __float2bfloat16(v1);
                    __nv_bfloat162 hh; hh.x = h0; hh.y = h1;
                    __nv_bfloat162 ll;
                    ll.x = __float2bfloat16(v0 - __bfloat162float(h0));
                    ll.y = __float2bfloat16(v1 - __bfloat162float(h1));
                    *(uint32_t*)(g_h1_hi + (size_t)mrow * N1 + nc) = *(uint32_t*)&hh;
                    *(uint32_t*)(g_h1_lo + (size_t)mrow * N1 + nc) = *(uint32_t*)&ll;
                } else {
                    int b = mrow >> 14, pix = mrow & (HWn - 1);
                    dout[(size_t)(b * N2 + nc) * HWn + pix]     = v0;
                    dout[(size_t)(b * N2 + nc + 1) * HWn + pix] = v1;
                }
            }
        }
    }
}

// -------------------- launch ------------------------------------------------
extern "C" void kernel_launch(void* const* d_in, const int* in_sizes, int n_in,
                              void* d_out, int out_size) {
    (void)in_sizes; (void)n_in; (void)out_size;
    const float* x   = (const float*)d_in[0];
    const float* g1  = (const float*)d_in[1];
    const float* be1 = (const float*)d_in[2];
    const float* mu1 = (const float*)d_in[3];
    const float* va1 = (const float*)d_in[4];
    const float* W1  = (const float*)d_in[5];
    const float* b1  = (const float*)d_in[6];
    const float* g2  = (const float*)d_in[7];
    const float* be2 = (const float*)d_in[8];
    const float* mu2 = (const float*)d_in[9];
    const float* va2 = (const float*)d_in[10];
    const float* W2  = (const float*)d_in[11];
    const float* b2  = (const float*)d_in[12];

    // smem sizes: SS = 2*(128*80) + 2*(BN*80); total = 2*SS + BN*4
    constexpr int S1 = 2 * (2 * 128 * 80 + 2 * 256 * 80) + 256 * 4;   // 123904
    constexpr int S2 = 2 * (2 * 128 * 80 + 2 * 96 * 80) + 96 * 4;     //  72064
    cudaFuncSetAttribute(k_gemm<KKP, 256, 8, 1>, cudaFuncAttributeMaxDynamicSharedMemorySize, S1);
    cudaFuncSetAttribute(k_gemm<N1, 96, 4, 2>,  cudaFuncAttributeMaxDynamicSharedMemorySize, S2);

    k_fold1<<<N1, 256>>>(W1, b1, g1, be1, mu1, va1);
    k_fold2<<<N2, 256>>>(W2, b2, g2, be2, mu2, va2);

    int nsat = Bn * Cn * SATR;
    k_sat_rows<<<(nsat + 127) / 128, 128>>>(x);
    k_sat_cols<<<(nsat + 127) / 128, 128>>>();

    k_features<<<dim3(Mtot / 64, KKP / 32), 256>>>(x);

    __nv_bfloat16 *ph, *pl, *w1h, *w1l, *h1h, *h1l, *w2h, *w2l;
    float *bb1, *bb2;
    cudaGetSymbolAddress((void**)&ph,  g_phi_hi);
    cudaGetSymbolAddress((void**)&pl,  g_phi_lo);
    cudaGetSymbolAddress((void**)&w1h, g_W1h);
    cudaGetSymbolAddress((void**)&w1l, g_W1l);
    cudaGetSymbolAddress((void**)&h1h, g_h1_hi);
    cudaGetSymbolAddress((void**)&h1l, g_h1_lo);
    cudaGetSymbolAddress((void**)&w2h, g_W2h);
    cudaGetSymbolAddress((void**)&w2l, g_W2l);
    cudaGetSymbolAddress((void**)&bb1, g_b1f);
    cudaGetSymbolAddress((void**)&bb2, g_b2f);

    k_gemm<KKP, 256, 8, 1><<<dim3(Mtot / 128, N1 / 256), 512, S1>>>(ph, pl, w1h, w1l, bb1, nullptr);
    k_gemm<N1, 96, 4, 2><<<dim3(Mtot / 128, 1), 256, S2>>>(h1h, h1l, w2h, w2l, bb2, (float*)d_out);
}